// round 10
// baseline (speedup 1.0000x reference)
#include <cuda_runtime.h>

#define T_STEPS 301
#define IN_DIM  40
#define H_DIM   64
#define G_DIM   256      // 4*H
#define KTOT    104      // IN + H
#define BTILE   32       // samples per CTA
#define NTHR    512      // 16 warps = 4 per SMSP
#define XST     36       // floats per operand row (32 samples + pad; 144 B, 16B-aligned)
#define TIN     (T_STEPS * IN_DIM)

// Shared memory layout (floats)
#define WQ_OFF   0
#define WQ_SIZE  (KTOT * G_DIM)          // 26624 : Wq[k][4*j+g]
#define XH_OFF   (WQ_OFF + WQ_SIZE)
#define XH_SIZE  (KTOT * XST)            // rows k<40: x_t, rows >=40: h_{t-1}
#define BIAS_OFF (XH_OFF + XH_SIZE)      // bq[4*j+g]
#define CLF_OFF  (BIAS_OFF + G_DIM)
#define SMEM_FLOATS (CLF_OFF + BTILE * 65)   // 32704 floats = 130816 B

typedef unsigned long long ull;

__device__ __forceinline__ ull pack2(float a, float b) {
    ull r; asm("mov.b64 %0, {%1,%2};" : "=l"(r) : "f"(a), "f"(b)); return r;
}
__device__ __forceinline__ void unpack2(ull v, float& a, float& b) {
    asm("mov.b64 {%0,%1}, %2;" : "=f"(a), "=f"(b) : "l"(v));
}
__device__ __forceinline__ void ffma2(ull& d, ull a, ull b) {
    asm("fma.rn.f32x2 %0, %1, %2, %0;" : "+l"(d) : "l"(a), "l"(b));
}
__device__ __forceinline__ float tanha(float x) {
    float y; asm("tanh.approx.f32 %0, %1;" : "=f"(y) : "f"(x)); return y;
}
__device__ __forceinline__ float sigm(float x) {
    return fmaf(0.5f, tanha(0.5f * x), 0.5f);
}

__global__ void __launch_bounds__(NTHR, 1)
lstm_fused_kernel(const float* __restrict__ x,
                  const float* __restrict__ w_ih,
                  const float* __restrict__ w_hh,
                  const float* __restrict__ b_ih,
                  const float* __restrict__ b_hh,
                  const float* __restrict__ w_clf,
                  const float* __restrict__ b_clf,
                  float* __restrict__ out)
{
    extern __shared__ float sm[];
    float* Wq    = sm + WQ_OFF;
    float* xhf   = sm + XH_OFF;
    float* bias  = sm + BIAS_OFF;
    float* shclf = sm + CLF_OFF;

    const int tid   = threadIdx.x;
    const int lane  = tid & 31;
    const int w     = tid >> 5;             // warp 0..15
    const int jblk  = w & 7;                // j block of 8
    const int shalf = w >> 3;               // sample half (16)
    const int j     = 8 * jblk + (lane >> 2);   // gate column 0..63
    const int sb    = 16 * shalf + 4 * (lane & 3); // first of 4 samples
    const int base  = blockIdx.x * BTILE;

    // ---- stage weights: Wq[k][4*j+g]  (warp's 8 j's -> 32 consecutive floats) ----
    for (int idx = tid; idx < WQ_SIZE; idx += NTHR) {
        int k = idx >> 8, r = idx & 255;
        int jj = r >> 2, g = r & 3;
        Wq[idx] = (k < IN_DIM) ? w_ih[(g * H_DIM + jj) * IN_DIM + k]
                               : w_hh[(g * H_DIM + jj) * H_DIM + (k - IN_DIM)];
    }
    if (tid < G_DIM) {
        int jj = tid >> 2, g = tid & 3;
        bias[tid] = b_ih[g * H_DIM + jj] + b_hh[g * H_DIM + jj];
    }
    // zero h rows (t=0 hidden state)
    for (int f = tid; f < H_DIM * BTILE; f += NTHR)
        xhf[(IN_DIM + (f >> 5)) * XST + (f & 31)] = 0.f;

    // ---- x staging: 1280 floats / 512 threads -> up to 3 each ----
    int xs[3], xk[3], xv[3];
    #pragma unroll
    for (int i = 0; i < 3; i++) {
        int f = tid + i * NTHR;
        xv[i] = (f < BTILE * IN_DIM);
        int ff = xv[i] ? f : 0;
        xs[i] = ff / IN_DIM;
        xk[i] = ff - xs[i] * IN_DIM;
    }
    const float* xbase = x + (size_t)base * TIN;

    float xr[3];
    #pragma unroll
    for (int i = 0; i < 3; i++)
        if (xv[i]) xr[i] = xbase[(size_t)xs[i] * TIN + xk[i]];   // x_0

    __syncthreads();   // weights + bias + h-zero visible

    // packed biases in registers (one float4 load)
    ull bp[4];
    {
        float4 bv = *(const float4*)(bias + 4 * j);
        bp[0] = pack2(bv.x, bv.x); bp[1] = pack2(bv.y, bv.y);
        bp[2] = pack2(bv.z, bv.z); bp[3] = pack2(bv.w, bv.w);
    }

    float c[4], clf[4];
    #pragma unroll
    for (int i = 0; i < 4; i++) { c[i] = 0.f; clf[i] = 0.f; }

    const float* wp = Wq + 4 * j;
    const float* xp = xhf + sb;

    for (int t = 0; t < T_STEPS; t++) {
        // stage x_t (x rows only; disjoint from h rows)
        #pragma unroll
        for (int i = 0; i < 3; i++)
            if (xv[i]) xhf[xk[i] * XST + xs[i]] = xr[i];
        // prefetch x_{t+1}
        if (t + 1 < T_STEPS) {
            #pragma unroll
            for (int i = 0; i < 3; i++)
                if (xv[i]) xr[i] = xbase[(size_t)xs[i] * TIN + (t + 1) * IN_DIM + xk[i]];
        }
        float wc = __ldg(&w_clf[t * H_DIM + j]);

        __syncthreads();   // x_t + h_{t-1} staged

        // ---- z = [x_t ; h_{t-1}] @ W^T : 104-deep, 8 f32x2 accumulators ----
        ull acc[4][2];
        #pragma unroll
        for (int g = 0; g < 4; g++) { acc[g][0] = bp[g]; acc[g][1] = bp[g]; }

        #pragma unroll 8
        for (int k = 0; k < KTOT; k++) {
            float4 wv = *(const float4*)(wp + k * G_DIM);        // 4 gate weights (1 phase/warp)
            ulonglong2 xv2 = *(const ulonglong2*)(xp + k * XST); // 4 samples (1 phase/warp)
            ull W0 = pack2(wv.x, wv.x), W1 = pack2(wv.y, wv.y);
            ull W2 = pack2(wv.z, wv.z), W3 = pack2(wv.w, wv.w);
            ffma2(acc[0][0], W0, xv2.x); ffma2(acc[0][1], W0, xv2.y);
            ffma2(acc[1][0], W1, xv2.x); ffma2(acc[1][1], W1, xv2.y);
            ffma2(acc[2][0], W2, xv2.x); ffma2(acc[2][1], W2, xv2.y);
            ffma2(acc[3][0], W3, xv2.x); ffma2(acc[3][1], W3, xv2.y);
        }

        __syncthreads();   // all GEMM reads of xhf done before h rows are overwritten

        // ---- gates: i,f,g,o all local for 4 samples ----
        float hv[4];
        #pragma unroll
        for (int p = 0; p < 2; p++) {
            float zi0, zi1, zf0, zf1, zg0, zg1, zo0, zo1;
            unpack2(acc[0][p], zi0, zi1);
            unpack2(acc[1][p], zf0, zf1);
            unpack2(acc[2][p], zg0, zg1);
            unpack2(acc[3][p], zo0, zo1);
            float cc0 = sigm(zf0) * c[2*p]   + sigm(zi0) * tanha(zg0);
            float cc1 = sigm(zf1) * c[2*p+1] + sigm(zi1) * tanha(zg1);
            c[2*p]   = cc0;  c[2*p+1] = cc1;
            hv[2*p]   = sigm(zo0) * tanha(cc0);
            hv[2*p+1] = sigm(zo1) * tanha(cc1);
            clf[2*p]   = fmaf(hv[2*p],   wc, clf[2*p]);
            clf[2*p+1] = fmaf(hv[2*p+1], wc, clf[2*p+1]);
        }
        // store h_t for this thread's (j, 4 samples): one STS.128
        *(float4*)(xhf + (IN_DIM + j) * XST + sb) =
            make_float4(hv[0], hv[1], hv[2], hv[3]);
    }

    // ---- classifier reduction over j ----
    __syncthreads();
    #pragma unroll
    for (int m = 0; m < 4; m++)
        shclf[(sb + m) * 65 + j] = clf[m];
    __syncthreads();
    if (tid < BTILE) {
        float s = b_clf[0];
        #pragma unroll 8
        for (int jj = 0; jj < H_DIM; jj++) s += shclf[tid * 65 + jj];
        out[base + tid] = s;
    }
}

extern "C" void kernel_launch(void* const* d_in, const int* in_sizes, int n_in,
                              void* d_out, int out_size)
{
    const float* x     = (const float*)d_in[0];
    const float* w_ih  = (const float*)d_in[1];
    const float* w_hh  = (const float*)d_in[2];
    const float* b_ih  = (const float*)d_in[3];
    const float* b_hh  = (const float*)d_in[4];
    const float* w_clf = (const float*)d_in[5];
    const float* b_clf = (const float*)d_in[6];
    float* out = (float*)d_out;

    const int B = in_sizes[0] / TIN;   // 4096
    const int smem_bytes = SMEM_FLOATS * sizeof(float);

    cudaFuncSetAttribute(lstm_fused_kernel,
                         cudaFuncAttributeMaxDynamicSharedMemorySize, smem_bytes);
    lstm_fused_kernel<<<B / BTILE, NTHR, smem_bytes>>>(
        x, w_ih, w_hh, b_ih, b_hh, w_clf, b_clf, out);
}